// round 14
// baseline (speedup 1.0000x reference)
#include <cuda_runtime.h>
#include <math.h>
#include <stdint.h>

// Problem constants: x[4,2048,1024], weights [1024,1024]
#define BB   4
#define SS   2048
#define DD   1024
#define HALF (DD / 2)

// ---------------------------------------------------------------------------
// Scratch (device globals — no cudaMalloc allowed)
// ---------------------------------------------------------------------------
__device__ float g_Q[BB * SS * DD];
__device__ float g_K[BB * SS * DD];
__device__ float g_V[BB * SS * DD];
__device__ float g_O[BB * SS * DD];
__device__ float g_Xr[BB * SS * DD];          // tf32-rounded x
__device__ float g_Wr[4 * DD * DD];           // tf32-rounded wq,wk,wv,wo
__device__ float g_P[(long)BB * SS * SS];     // attention scores / probs
__device__ float g_cos[SS * HALF];
__device__ float g_sin[SS * HALF];

__device__ __forceinline__ uint32_t f2tf(float f) {
    uint32_t u;
    asm("cvt.rna.tf32.f32 %0, %1;" : "=r"(u) : "f"(f));
    return u;
}
__device__ __forceinline__ float rtf(float f) { return __uint_as_float(f2tf(f)); }

// ---------------------------------------------------------------------------
// Elementwise tf32 rounding (float4 vectorized)
// ---------------------------------------------------------------------------
__global__ void round_tf32_kernel(const float* __restrict__ in,
                                  float* __restrict__ out, int n4) {
    int i = blockIdx.x * blockDim.x + threadIdx.x;
    if (i < n4) {
        float4 v = ((const float4*)in)[i];
        v.x = rtf(v.x); v.y = rtf(v.y); v.z = rtf(v.z); v.w = rtf(v.w);
        ((float4*)out)[i] = v;
    }
}

// ---------------------------------------------------------------------------
// RoPE cos/sin tables.  grid = SS, block = HALF
// ---------------------------------------------------------------------------
__global__ void rope_table_kernel(float* __restrict__ ct, float* __restrict__ st) {
    int s = blockIdx.x;
    int p = threadIdx.x;
    double inv = exp(-((double)(2 * p) / (double)DD) * log(10000.0));
    double ang = (double)s * inv;
    ct[s * HALF + p] = (float)cos(ang);
    st[s * HALF + p] = (float)sin(ang);
}

// ---------------------------------------------------------------------------
// Row softmax over length SS; outputs tf32-rounded. grid = BB*SS, block = 256
// ---------------------------------------------------------------------------
__global__ void softmax_kernel(float* __restrict__ P) {
    float* row = P + (long)blockIdx.x * SS;
    int t = threadIdx.x;
    float v[8];
    float m = -1e30f;
#pragma unroll
    for (int j = 0; j < 8; j++) {
        v[j] = row[t + 256 * j];
        m = fmaxf(m, v[j]);
    }
    __shared__ float red[8];
#pragma unroll
    for (int o = 16; o > 0; o >>= 1)
        m = fmaxf(m, __shfl_xor_sync(0xffffffffu, m, o));
    if ((t & 31) == 0) red[t >> 5] = m;
    __syncthreads();
    m = red[0];
#pragma unroll
    for (int i = 1; i < 8; i++) m = fmaxf(m, red[i]);

    float sum = 0.f;
#pragma unroll
    for (int j = 0; j < 8; j++) {
        v[j] = expf(v[j] - m);
        sum += v[j];
    }
#pragma unroll
    for (int o = 16; o > 0; o >>= 1)
        sum += __shfl_xor_sync(0xffffffffu, sum, o);
    __syncthreads();
    if ((t & 31) == 0) red[t >> 5] = sum;
    __syncthreads();
    sum = 0.f;
#pragma unroll
    for (int i = 0; i < 8; i++) sum += red[i];
    float inv = 1.0f / sum;
#pragma unroll
    for (int j = 0; j < 8; j++) row[t + 256 * j] = rtf(v[j] * inv);
}

// ---------------------------------------------------------------------------
// TF32 tensor-core GEMM, 4-stage cp.async pipeline.
// 128x128 CTA tile, BK=16, 4 warps (128 threads), 64x64 warp tiles,
// mma.sync.m16n8k8.tf32. Inputs must be pre-rounded to tf32.
//   BT = true : C = alpha * A[M,K] @ B[N,K]^T
//   BT = false: C = alpha * A[M,K] @ B[K,N]
// mode: 0 = plain store, 1 = tf32-round store, 2 = RoPE + round (alpha==1)
// M,N % 128 == 0; K % 16 == 0, K >= 48.  grid = (N/128, M/128, batch)
// ---------------------------------------------------------------------------
#define CP16(dst_u32, src_ptr) \
    asm volatile("cp.async.cg.shared.global [%0], [%1], 16;" \
                 :: "r"(dst_u32), "l"(src_ptr))
#define CP_COMMIT() asm volatile("cp.async.commit_group;")
#define CP_WAIT2()  asm volatile("cp.async.wait_group 2;")

template <bool BT>
__global__ void __launch_bounds__(128)
tf32_gemm(const float* __restrict__ A, const float* __restrict__ Bm,
          float* __restrict__ C, int M, int N, int K,
          long sA, long sB, long sC, float alpha, int mode,
          const float* __restrict__ CT, const float* __restrict__ ST) {
    A  += (long)blockIdx.z * sA;
    Bm += (long)blockIdx.z * sB;
    C  += (long)blockIdx.z * sC;
    const int m0 = blockIdx.y * 128;
    const int n0 = blockIdx.x * 128;

    // Conflict-free padded strides:
    //   [row][k] tiles: stride 20 -> bank (20r + c) % 32 all-distinct
    //   [k][n]  tile (NN B): stride 136 -> bank (8k + n) % 32 all-distinct
    constexpr int A_STAGE = 128 * 20;
    constexpr int B_STAGE = BT ? 128 * 20 : 16 * 136;
    constexpr int STAGES  = 4;

    extern __shared__ float smem[];
    float* AsAll = smem;
    float* BsAll = smem + STAGES * A_STAGE;

    uint32_t smem_u32;
    asm("{ .reg .u64 t; cvta.to.shared.u64 t, %1; cvt.u32.u64 %0, t; }"
        : "=r"(smem_u32) : "l"(smem));
    const uint32_t asBase = smem_u32;
    const uint32_t bsBase = smem_u32 + (uint32_t)STAGES * A_STAGE * 4u;

    const int t    = threadIdx.x;
    const int lane = t & 31;
    const int warp = t >> 5;       // 0..3
    const int wm   = warp & 1;     // m offset wm*64
    const int wn   = warp >> 1;    // n offset wn*64
    const int g    = lane >> 2;    // 0..7
    const int tg   = lane & 3;     // 0..3

    float acc[4][8][4];
#pragma unroll
    for (int i = 0; i < 4; i++)
#pragma unroll
        for (int j = 0; j < 8; j++)
#pragma unroll
            for (int r = 0; r < 4; r++) acc[i][j][r] = 0.f;

    // copy descriptors: 4 x 16B per operand per stage (128 threads)
    int aRow[4], aC4[4], bRowNN[4], bC4NN[4];
#pragma unroll
    for (int r = 0; r < 4; r++) {
        int id = t + 128 * r;      // 0..511
        aRow[r]   = id >> 2;       // 0..127
        aC4[r]    = id & 3;        // 0..3
        bRowNN[r] = id >> 5;       // 0..15
        bC4NN[r]  = id & 31;       // 0..31
    }

    const int nk = K / 16;

    auto issue = [&](int kb_, int st) {
        const int ko = kb_ * 16;
#pragma unroll
        for (int r = 0; r < 4; r++) {
            const float* srcA = A + (long)(m0 + aRow[r]) * K + ko + aC4[r] * 4;
            uint32_t dA = asBase + (uint32_t)(st * A_STAGE + aRow[r] * 20 + aC4[r] * 4) * 4u;
            CP16(dA, srcA);
            if (BT) {
                const float* srcB = Bm + (long)(n0 + aRow[r]) * K + ko + aC4[r] * 4;
                uint32_t dB = bsBase + (uint32_t)(st * B_STAGE + aRow[r] * 20 + aC4[r] * 4) * 4u;
                CP16(dB, srcB);
            } else {
                const float* srcB = Bm + (long)(ko + bRowNN[r]) * N + n0 + bC4NN[r] * 4;
                uint32_t dB = bsBase + (uint32_t)(st * B_STAGE + bRowNN[r] * 136 + bC4NN[r] * 4) * 4u;
                CP16(dB, srcB);
            }
        }
        CP_COMMIT();
    };

    // prologue: stages 0,1,2
    issue(0, 0);
    issue(1, 1);
    issue(2, 2);
    CP_WAIT2();
    __syncthreads();

    int buf = 0;
    for (int kb = 0; kb < nk; kb++) {
        const float* AsB = AsAll + buf * A_STAGE;
        const float* BsB = BsAll + buf * B_STAGE;

#pragma unroll
        for (int ks = 0; ks < 2; ks++) {
            uint32_t af[4][4], bf[8][2];
            const int c0 = ks * 8 + tg;
            const int r0 = wm * 64 + g;
#pragma unroll
            for (int i = 0; i < 4; i++) {
                const float* p = &AsB[(r0 + i * 16) * 20 + c0];
                af[i][0] = __float_as_uint(p[0]);
                af[i][1] = __float_as_uint(p[8 * 20]);
                af[i][2] = __float_as_uint(p[4]);
                af[i][3] = __float_as_uint(p[8 * 20 + 4]);
            }
#pragma unroll
            for (int j = 0; j < 8; j++) {
                const int col = wn * 64 + j * 8 + g;
                if (BT) {
                    bf[j][0] = __float_as_uint(BsB[col * 20 + c0]);
                    bf[j][1] = __float_as_uint(BsB[col * 20 + c0 + 4]);
                } else {
                    bf[j][0] = __float_as_uint(BsB[c0 * 136 + col]);
                    bf[j][1] = __float_as_uint(BsB[(c0 + 4) * 136 + col]);
                }
            }
#pragma unroll
            for (int i = 0; i < 4; i++)
#pragma unroll
                for (int j = 0; j < 8; j++) {
                    asm volatile(
                        "mma.sync.aligned.m16n8k8.row.col.f32.tf32.tf32.f32 "
                        "{%0,%1,%2,%3}, {%4,%5,%6,%7}, {%8,%9}, {%0,%1,%2,%3};"
                        : "+f"(acc[i][j][0]), "+f"(acc[i][j][1]),
                          "+f"(acc[i][j][2]), "+f"(acc[i][j][3])
                        : "r"(af[i][0]), "r"(af[i][1]), "r"(af[i][2]), "r"(af[i][3]),
                          "r"(bf[j][0]), "r"(bf[j][1]));
                }
        }

        if (kb + 3 < nk) issue(kb + 3, (kb + 3) & 3);
        else             CP_COMMIT();   // empty group keeps wait arithmetic exact
        CP_WAIT2();
        __syncthreads();
        buf = (buf + 1) & 3;
    }

    // ---- epilogue ----
#pragma unroll
    for (int i = 0; i < 4; i++)
#pragma unroll
        for (int j = 0; j < 8; j++) {
            const int row = m0 + wm * 64 + i * 16 + g;
            const int col = n0 + wn * 64 + j * 8 + 2 * tg;
            float s0 = acc[i][j][0] * alpha, s1 = acc[i][j][1] * alpha;
            float s2 = acc[i][j][2] * alpha, s3 = acc[i][j][3] * alpha;
            if (mode == 2) {
                // RoPE on the (even, odd) column pair, then tf32-round.
                const int p  = col >> 1;
                const int sq0 = row & (SS - 1);
                const int sq1 = (row + 8) & (SS - 1);
                float c0v = CT[sq0 * HALF + p], s0v = ST[sq0 * HALF + p];
                float c1v = CT[sq1 * HALF + p], s1v = ST[sq1 * HALF + p];
                float o0 = s0 * c0v - s1 * s0v;
                float o1 = s0 * s0v + s1 * c0v;
                float o2 = s2 * c1v - s3 * s1v;
                float o3 = s2 * s1v + s3 * c1v;
                s0 = rtf(o0); s1 = rtf(o1); s2 = rtf(o2); s3 = rtf(o3);
            } else if (mode == 1) {
                s0 = rtf(s0); s1 = rtf(s1); s2 = rtf(s2); s3 = rtf(s3);
            }
            *(float2*)(C + (long)row * N + col)       = make_float2(s0, s1);
            *(float2*)(C + (long)(row + 8) * N + col) = make_float2(s2, s3);
        }
}

// ---------------------------------------------------------------------------
// kernel_launch: x, wq, wk, wv, wo  ->  out [B,S,D] fp32
// ---------------------------------------------------------------------------
extern "C" void kernel_launch(void* const* d_in, const int* in_sizes, int n_in,
                              void* d_out, int out_size) {
    const float* x  = (const float*)d_in[0];
    const float* w_in[4] = {(const float*)d_in[1], (const float*)d_in[2],
                            (const float*)d_in[3], (const float*)d_in[4]};
    float* out = (float*)d_out;

    float *Q, *K, *V, *O, *Xr, *Wr, *P, *CT, *ST;
    cudaGetSymbolAddress((void**)&Q,  g_Q);
    cudaGetSymbolAddress((void**)&K,  g_K);
    cudaGetSymbolAddress((void**)&V,  g_V);
    cudaGetSymbolAddress((void**)&O,  g_O);
    cudaGetSymbolAddress((void**)&Xr, g_Xr);
    cudaGetSymbolAddress((void**)&Wr, g_Wr);
    cudaGetSymbolAddress((void**)&P,  g_P);
    cudaGetSymbolAddress((void**)&CT, g_cos);
    cudaGetSymbolAddress((void**)&ST, g_sin);

    const long SD  = (long)SS * DD;
    const long SSs = (long)SS * SS;

    // dynamic smem sizes (4 stages)
    const int smemBT = 4 * (128 * 20 + 128 * 20) * 4;   // 81920
    const int smemNN = 4 * (128 * 20 + 16 * 136) * 4;   // 75776
    cudaFuncSetAttribute(tf32_gemm<true>,
                         cudaFuncAttributeMaxDynamicSharedMemorySize, smemBT);
    cudaFuncSetAttribute(tf32_gemm<false>,
                         cudaFuncAttributeMaxDynamicSharedMemorySize, smemNN);

    rope_table_kernel<<<SS, HALF>>>(CT, ST);

    // pre-round inputs to tf32
    {
        int n4 = BB * SS * DD / 4;
        round_tf32_kernel<<<(n4 + 255) / 256, 256>>>(x, Xr, n4);
        int w4 = DD * DD / 4;
        for (int i = 0; i < 4; i++)
            round_tf32_kernel<<<(w4 + 255) / 256, 256>>>(w_in[i], Wr + (long)i * DD * DD, w4);
    }
    const float* wq = Wr;
    const float* wk = Wr + (long)DD * DD;
    const float* wv = Wr + 2L * DD * DD;
    const float* wo = Wr + 3L * DD * DD;

    // Q/K/V projections (RoPE fused into Q/K epilogues)
    dim3 gProj(DD / 128, (BB * SS) / 128, 1);
    tf32_gemm<true><<<gProj, 128, smemBT>>>(Xr, wq, Q, BB * SS, DD, DD, 0, 0, 0, 1.0f, 2, CT, ST);
    tf32_gemm<true><<<gProj, 128, smemBT>>>(Xr, wk, K, BB * SS, DD, DD, 0, 0, 0, 1.0f, 2, CT, ST);
    tf32_gemm<true><<<gProj, 128, smemBT>>>(Xr, wv, V, BB * SS, DD, DD, 0, 0, 0, 1.0f, 1, CT, ST);

    // scores = (Q @ K^T) / 32, batched over B
    dim3 gScore(SS / 128, SS / 128, BB);
    tf32_gemm<true><<<gScore, 128, smemBT>>>(Q, K, P, SS, SS, DD, SD, SD, SSs, 0.03125f, 0, CT, ST);

    softmax_kernel<<<BB * SS, 256>>>(P);   // rounds P

    // O = P @ V (NN), batched; round O for final GEMM
    dim3 gPV(DD / 128, SS / 128, BB);
    tf32_gemm<false><<<gPV, 128, smemNN>>>(P, V, O, SS, DD, SS, SSs, SD, SD, 1.0f, 1, CT, ST);

    // out = O @ wo^T
    tf32_gemm<true><<<gProj, 128, smemBT>>>(O, wo, out, BB * SS, DD, DD, 0, 0, 0, 1.0f, 0, CT, ST);
}

// round 15
// speedup vs baseline: 1.0006x; 1.0006x over previous
#include <cuda_runtime.h>
#include <math.h>
#include <stdint.h>

// Problem constants: x[4,2048,1024], weights [1024,1024]
#define BB   4
#define SS   2048
#define DD   1024
#define HALF (DD / 2)

// ---------------------------------------------------------------------------
// Scratch (device globals — no cudaMalloc allowed)
// ---------------------------------------------------------------------------
__device__ float g_Q[BB * SS * DD];
__device__ float g_K[BB * SS * DD];
__device__ float g_V[BB * SS * DD];
__device__ float g_O[BB * SS * DD];
__device__ float g_Xr[BB * SS * DD];          // tf32-rounded x
__device__ float g_Wr[4 * DD * DD];           // tf32-rounded wq,wk,wv,wo
__device__ float g_P[(long)BB * SS * SS];     // attention scores / probs
__device__ float g_cos[SS * HALF];
__device__ float g_sin[SS * HALF];

__device__ __forceinline__ uint32_t f2tf(float f) {
    uint32_t u;
    asm("cvt.rna.tf32.f32 %0, %1;" : "=r"(u) : "f"(f));
    return u;
}
__device__ __forceinline__ float rtf(float f) { return __uint_as_float(f2tf(f)); }

// ---------------------------------------------------------------------------
// Elementwise tf32 rounding (float4 vectorized)
// ---------------------------------------------------------------------------
__global__ void round_tf32_kernel(const float* __restrict__ in,
                                  float* __restrict__ out, int n4) {
    int i = blockIdx.x * blockDim.x + threadIdx.x;
    if (i < n4) {
        float4 v = ((const float4*)in)[i];
        v.x = rtf(v.x); v.y = rtf(v.y); v.z = rtf(v.z); v.w = rtf(v.w);
        ((float4*)out)[i] = v;
    }
}

// ---------------------------------------------------------------------------
// RoPE cos/sin tables.  grid = SS, block = HALF
// ---------------------------------------------------------------------------
__global__ void rope_table_kernel(float* __restrict__ ct, float* __restrict__ st) {
    int s = blockIdx.x;
    int p = threadIdx.x;
    double inv = exp(-((double)(2 * p) / (double)DD) * log(10000.0));
    double ang = (double)s * inv;
    ct[s * HALF + p] = (float)cos(ang);
    st[s * HALF + p] = (float)sin(ang);
}

// ---------------------------------------------------------------------------
// Row softmax over length SS; outputs tf32-rounded. grid = BB*SS, block = 256
// ---------------------------------------------------------------------------
__global__ void softmax_kernel(float* __restrict__ P) {
    float* row = P + (long)blockIdx.x * SS;
    int t = threadIdx.x;
    float v[8];
    float m = -1e30f;
#pragma unroll
    for (int j = 0; j < 8; j++) {
        v[j] = row[t + 256 * j];
        m = fmaxf(m, v[j]);
    }
    __shared__ float red[8];
#pragma unroll
    for (int o = 16; o > 0; o >>= 1)
        m = fmaxf(m, __shfl_xor_sync(0xffffffffu, m, o));
    if ((t & 31) == 0) red[t >> 5] = m;
    __syncthreads();
    m = red[0];
#pragma unroll
    for (int i = 1; i < 8; i++) m = fmaxf(m, red[i]);

    float sum = 0.f;
#pragma unroll
    for (int j = 0; j < 8; j++) {
        v[j] = expf(v[j] - m);
        sum += v[j];
    }
#pragma unroll
    for (int o = 16; o > 0; o >>= 1)
        sum += __shfl_xor_sync(0xffffffffu, sum, o);
    __syncthreads();
    if ((t & 31) == 0) red[t >> 5] = sum;
    __syncthreads();
    sum = 0.f;
#pragma unroll
    for (int i = 0; i < 8; i++) sum += red[i];
    float inv = 1.0f / sum;
#pragma unroll
    for (int j = 0; j < 8; j++) row[t + 256 * j] = rtf(v[j] * inv);
}

// ---------------------------------------------------------------------------
// TF32 tensor-core GEMM, 4-stage cp.async pipeline.
// 128x128 CTA tile, BK=16, 4 warps (128 threads), 64x64 warp tiles,
// mma.sync.m16n8k8.tf32. Inputs must be pre-rounded to tf32.
//   BT = true : C = alpha * A[M,K] @ B[N,K]^T
//   BT = false: C = alpha * A[M,K] @ B[K,N]
// mode: 0 = plain store, 1 = tf32-round store, 2 = RoPE + round (alpha==1)
// M,N % 128 == 0; K % 16 == 0, K >= 48.  grid = (N/128, M/128, batch)
// ---------------------------------------------------------------------------
#define CP16(dst_u32, src_ptr) \
    asm volatile("cp.async.cg.shared.global [%0], [%1], 16;" \
                 :: "r"(dst_u32), "l"(src_ptr))
#define CP_COMMIT() asm volatile("cp.async.commit_group;")
#define CP_WAIT2()  asm volatile("cp.async.wait_group 2;")

template <bool BT>
__global__ void __launch_bounds__(128)
tf32_gemm(const float* __restrict__ A, const float* __restrict__ Bm,
          float* __restrict__ C, int M, int N, int K,
          long sA, long sB, long sC, float alpha, int mode,
          const float* __restrict__ CT, const float* __restrict__ ST) {
    A  += (long)blockIdx.z * sA;
    Bm += (long)blockIdx.z * sB;
    C  += (long)blockIdx.z * sC;
    const int m0 = blockIdx.y * 128;
    const int n0 = blockIdx.x * 128;

    // Conflict-free padded strides:
    //   [row][k] tiles: stride 20 -> bank (20r + c) % 32 all-distinct
    //   [k][n]  tile (NN B): stride 136 -> bank (8k + n) % 32 all-distinct
    constexpr int A_STAGE = 128 * 20;
    constexpr int B_STAGE = BT ? 128 * 20 : 16 * 136;
    constexpr int STAGES  = 4;

    extern __shared__ float smem[];
    float* AsAll = smem;
    float* BsAll = smem + STAGES * A_STAGE;

    uint32_t smem_u32;
    asm("{ .reg .u64 t; cvta.to.shared.u64 t, %1; cvt.u32.u64 %0, t; }"
        : "=r"(smem_u32) : "l"(smem));
    const uint32_t asBase = smem_u32;
    const uint32_t bsBase = smem_u32 + (uint32_t)STAGES * A_STAGE * 4u;

    const int t    = threadIdx.x;
    const int lane = t & 31;
    const int warp = t >> 5;       // 0..3
    const int wm   = warp & 1;     // m offset wm*64
    const int wn   = warp >> 1;    // n offset wn*64
    const int g    = lane >> 2;    // 0..7
    const int tg   = lane & 3;     // 0..3

    float acc[4][8][4];
#pragma unroll
    for (int i = 0; i < 4; i++)
#pragma unroll
        for (int j = 0; j < 8; j++)
#pragma unroll
            for (int r = 0; r < 4; r++) acc[i][j][r] = 0.f;

    // copy descriptors: 4 x 16B per operand per stage (128 threads)
    int aRow[4], aC4[4], bRowNN[4], bC4NN[4];
#pragma unroll
    for (int r = 0; r < 4; r++) {
        int id = t + 128 * r;      // 0..511
        aRow[r]   = id >> 2;       // 0..127
        aC4[r]    = id & 3;        // 0..3
        bRowNN[r] = id >> 5;       // 0..15
        bC4NN[r]  = id & 31;       // 0..31
    }

    const int nk = K / 16;

    auto issue = [&](int kb_, int st) {
        const int ko = kb_ * 16;
#pragma unroll
        for (int r = 0; r < 4; r++) {
            const float* srcA = A + (long)(m0 + aRow[r]) * K + ko + aC4[r] * 4;
            uint32_t dA = asBase + (uint32_t)(st * A_STAGE + aRow[r] * 20 + aC4[r] * 4) * 4u;
            CP16(dA, srcA);
            if (BT) {
                const float* srcB = Bm + (long)(n0 + aRow[r]) * K + ko + aC4[r] * 4;
                uint32_t dB = bsBase + (uint32_t)(st * B_STAGE + aRow[r] * 20 + aC4[r] * 4) * 4u;
                CP16(dB, srcB);
            } else {
                const float* srcB = Bm + (long)(ko + bRowNN[r]) * N + n0 + bC4NN[r] * 4;
                uint32_t dB = bsBase + (uint32_t)(st * B_STAGE + bRowNN[r] * 136 + bC4NN[r] * 4) * 4u;
                CP16(dB, srcB);
            }
        }
        CP_COMMIT();
    };

    // prologue: stages 0,1,2
    issue(0, 0);
    issue(1, 1);
    issue(2, 2);
    CP_WAIT2();
    __syncthreads();

    int buf = 0;
    for (int kb = 0; kb < nk; kb++) {
        const float* AsB = AsAll + buf * A_STAGE;
        const float* BsB = BsAll + buf * B_STAGE;

#pragma unroll
        for (int ks = 0; ks < 2; ks++) {
            uint32_t af[4][4], bf[8][2];
            const int c0 = ks * 8 + tg;
            const int r0 = wm * 64 + g;
#pragma unroll
            for (int i = 0; i < 4; i++) {
                const float* p = &AsB[(r0 + i * 16) * 20 + c0];
                af[i][0] = __float_as_uint(p[0]);
                af[i][1] = __float_as_uint(p[8 * 20]);
                af[i][2] = __float_as_uint(p[4]);
                af[i][3] = __float_as_uint(p[8 * 20 + 4]);
            }
#pragma unroll
            for (int j = 0; j < 8; j++) {
                const int col = wn * 64 + j * 8 + g;
                if (BT) {
                    bf[j][0] = __float_as_uint(BsB[col * 20 + c0]);
                    bf[j][1] = __float_as_uint(BsB[col * 20 + c0 + 4]);
                } else {
                    bf[j][0] = __float_as_uint(BsB[c0 * 136 + col]);
                    bf[j][1] = __float_as_uint(BsB[(c0 + 4) * 136 + col]);
                }
            }
#pragma unroll
            for (int i = 0; i < 4; i++)
#pragma unroll
                for (int j = 0; j < 8; j++) {
                    asm volatile(
                        "mma.sync.aligned.m16n8k8.row.col.f32.tf32.tf32.f32 "
                        "{%0,%1,%2,%3}, {%4,%5,%6,%7}, {%8,%9}, {%0,%1,%2,%3};"
                        : "+f"(acc[i][j][0]), "+f"(acc[i][j][1]),
                          "+f"(acc[i][j][2]), "+f"(acc[i][j][3])
                        : "r"(af[i][0]), "r"(af[i][1]), "r"(af[i][2]), "r"(af[i][3]),
                          "r"(bf[j][0]), "r"(bf[j][1]));
                }
        }

        if (kb + 3 < nk) issue(kb + 3, (kb + 3) & 3);
        else             CP_COMMIT();   // empty group keeps wait arithmetic exact
        CP_WAIT2();
        __syncthreads();
        buf = (buf + 1) & 3;
    }

    // ---- epilogue ----
#pragma unroll
    for (int i = 0; i < 4; i++)
#pragma unroll
        for (int j = 0; j < 8; j++) {
            const int row = m0 + wm * 64 + i * 16 + g;
            const int col = n0 + wn * 64 + j * 8 + 2 * tg;
            float s0 = acc[i][j][0] * alpha, s1 = acc[i][j][1] * alpha;
            float s2 = acc[i][j][2] * alpha, s3 = acc[i][j][3] * alpha;
            if (mode == 2) {
                // RoPE on the (even, odd) column pair, then tf32-round.
                const int p  = col >> 1;
                const int sq0 = row & (SS - 1);
                const int sq1 = (row + 8) & (SS - 1);
                float c0v = CT[sq0 * HALF + p], s0v = ST[sq0 * HALF + p];
                float c1v = CT[sq1 * HALF + p], s1v = ST[sq1 * HALF + p];
                float o0 = s0 * c0v - s1 * s0v;
                float o1 = s0 * s0v + s1 * c0v;
                float o2 = s2 * c1v - s3 * s1v;
                float o3 = s2 * s1v + s3 * c1v;
                s0 = rtf(o0); s1 = rtf(o1); s2 = rtf(o2); s3 = rtf(o3);
            } else if (mode == 1) {
                s0 = rtf(s0); s1 = rtf(s1); s2 = rtf(s2); s3 = rtf(s3);
            }
            *(float2*)(C + (long)row * N + col)       = make_float2(s0, s1);
            *(float2*)(C + (long)(row + 8) * N + col) = make_float2(s2, s3);
        }
}

// ---------------------------------------------------------------------------
// kernel_launch: x, wq, wk, wv, wo  ->  out [B,S,D] fp32
// ---------------------------------------------------------------------------
extern "C" void kernel_launch(void* const* d_in, const int* in_sizes, int n_in,
                              void* d_out, int out_size) {
    const float* x  = (const float*)d_in[0];
    const float* w_in[4] = {(const float*)d_in[1], (const float*)d_in[2],
                            (const float*)d_in[3], (const float*)d_in[4]};
    float* out = (float*)d_out;

    float *Q, *K, *V, *O, *Xr, *Wr, *P, *CT, *ST;
    cudaGetSymbolAddress((void**)&Q,  g_Q);
    cudaGetSymbolAddress((void**)&K,  g_K);
    cudaGetSymbolAddress((void**)&V,  g_V);
    cudaGetSymbolAddress((void**)&O,  g_O);
    cudaGetSymbolAddress((void**)&Xr, g_Xr);
    cudaGetSymbolAddress((void**)&Wr, g_Wr);
    cudaGetSymbolAddress((void**)&P,  g_P);
    cudaGetSymbolAddress((void**)&CT, g_cos);
    cudaGetSymbolAddress((void**)&ST, g_sin);

    const long SD  = (long)SS * DD;
    const long SSs = (long)SS * SS;

    // dynamic smem sizes (4 stages)
    const int smemBT = 4 * (128 * 20 + 128 * 20) * 4;   // 81920
    const int smemNN = 4 * (128 * 20 + 16 * 136) * 4;   // 75776
    cudaFuncSetAttribute(tf32_gemm<true>,
                         cudaFuncAttributeMaxDynamicSharedMemorySize, smemBT);
    cudaFuncSetAttribute(tf32_gemm<false>,
                         cudaFuncAttributeMaxDynamicSharedMemorySize, smemNN);

    rope_table_kernel<<<SS, HALF>>>(CT, ST);

    // pre-round inputs to tf32
    {
        int n4 = BB * SS * DD / 4;
        round_tf32_kernel<<<(n4 + 255) / 256, 256>>>(x, Xr, n4);
        int w4 = DD * DD / 4;
        for (int i = 0; i < 4; i++)
            round_tf32_kernel<<<(w4 + 255) / 256, 256>>>(w_in[i], Wr + (long)i * DD * DD, w4);
    }
    const float* wq = Wr;
    const float* wk = Wr + (long)DD * DD;
    const float* wv = Wr + 2L * DD * DD;
    const float* wo = Wr + 3L * DD * DD;

    // Q/K/V projections (RoPE fused into Q/K epilogues)
    dim3 gProj(DD / 128, (BB * SS) / 128, 1);
    tf32_gemm<true><<<gProj, 128, smemBT>>>(Xr, wq, Q, BB * SS, DD, DD, 0, 0, 0, 1.0f, 2, CT, ST);
    tf32_gemm<true><<<gProj, 128, smemBT>>>(Xr, wk, K, BB * SS, DD, DD, 0, 0, 0, 1.0f, 2, CT, ST);
    tf32_gemm<true><<<gProj, 128, smemBT>>>(Xr, wv, V, BB * SS, DD, DD, 0, 0, 0, 1.0f, 1, CT, ST);

    // scores = (Q @ K^T) / 32, batched over B
    dim3 gScore(SS / 128, SS / 128, BB);
    tf32_gemm<true><<<gScore, 128, smemBT>>>(Q, K, P, SS, SS, DD, SD, SD, SSs, 0.03125f, 0, CT, ST);

    softmax_kernel<<<BB * SS, 256>>>(P);   // rounds P

    // O = P @ V (NN), batched; round O for final GEMM
    dim3 gPV(DD / 128, SS / 128, BB);
    tf32_gemm<false><<<gPV, 128, smemNN>>>(P, V, O, SS, DD, SS, SSs, SD, SD, 1.0f, 1, CT, ST);

    // out = O @ wo^T
    tf32_gemm<true><<<gProj, 128, smemBT>>>(O, wo, out, BB * SS, DD, DD, 0, 0, 0, 1.0f, 0, CT, ST);
}

// round 16
// speedup vs baseline: 1.6358x; 1.6349x over previous
#include <cuda_runtime.h>
#include <cuda_fp16.h>
#include <math.h>
#include <stdint.h>

// Problem constants: x[4,2048,1024], weights [1024,1024]
#define BB   4
#define SS   2048
#define DD   1024
#define HALFD (DD / 2)

// ---------------------------------------------------------------------------
// Scratch (device globals — no cudaMalloc allowed)
// ---------------------------------------------------------------------------
__device__ __half g_Q [BB * SS * DD];
__device__ __half g_K [BB * SS * DD];
__device__ __half g_Vt[BB * DD * SS];          // V transposed per batch [D][S]
__device__ __half g_O [BB * SS * DD];
__device__ __half g_Xh[BB * SS * DD];          // fp16 x
__device__ __half g_Wh[4 * DD * DD];           // fp16 wq,wk,wv,wo
__device__ __half g_P [(long)BB * SS * SS];    // scores / probs
__device__ float  g_cos[SS * HALFD];
__device__ float  g_sin[SS * HALFD];

// ---------------------------------------------------------------------------
// fp32 -> fp16 conversion, float4 -> 2x half2 per thread
// ---------------------------------------------------------------------------
__global__ void to_half_kernel(const float* __restrict__ in,
                               __half* __restrict__ out, int n4) {
    int i = blockIdx.x * blockDim.x + threadIdx.x;
    if (i < n4) {
        float4 v = ((const float4*)in)[i];
        ((__half2*)out)[2 * i]     = __floats2half2_rn(v.x, v.y);
        ((__half2*)out)[2 * i + 1] = __floats2half2_rn(v.z, v.w);
    }
}

// ---------------------------------------------------------------------------
// RoPE cos/sin tables.  grid = SS, block = HALFD
// ---------------------------------------------------------------------------
__global__ void rope_table_kernel(float* __restrict__ ct, float* __restrict__ st) {
    int s = blockIdx.x;
    int p = threadIdx.x;
    double inv = exp(-((double)(2 * p) / (double)DD) * log(10000.0));
    double ang = (double)s * inv;
    ct[s * HALFD + p] = (float)cos(ang);
    st[s * HALFD + p] = (float)sin(ang);
}

// ---------------------------------------------------------------------------
// Row softmax over length SS on fp16 data. grid = BB*SS rows, block = 256
// ---------------------------------------------------------------------------
__global__ void softmax_h_kernel(__half* __restrict__ P) {
    __half2* row = (__half2*)(P + (long)blockIdx.x * SS);   // 1024 half2
    int t = threadIdx.x;
    float2 v[4];
    float m = -1e30f;
#pragma unroll
    for (int j = 0; j < 4; j++) {
        v[j] = __half22float2(row[t + 256 * j]);
        m = fmaxf(m, fmaxf(v[j].x, v[j].y));
    }
    __shared__ float red[8];
#pragma unroll
    for (int o = 16; o > 0; o >>= 1)
        m = fmaxf(m, __shfl_xor_sync(0xffffffffu, m, o));
    if ((t & 31) == 0) red[t >> 5] = m;
    __syncthreads();
    m = red[0];
#pragma unroll
    for (int i = 1; i < 8; i++) m = fmaxf(m, red[i]);

    float sum = 0.f;
#pragma unroll
    for (int j = 0; j < 4; j++) {
        v[j].x = expf(v[j].x - m);
        v[j].y = expf(v[j].y - m);
        sum += v[j].x + v[j].y;
    }
#pragma unroll
    for (int o = 16; o > 0; o >>= 1)
        sum += __shfl_xor_sync(0xffffffffu, sum, o);
    __syncthreads();                 // all max-reads of red[] done
    if ((t & 31) == 0) red[t >> 5] = sum;
    __syncthreads();
    sum = 0.f;
#pragma unroll
    for (int i = 0; i < 8; i++) sum += red[i];
    float inv = 1.0f / sum;
#pragma unroll
    for (int j = 0; j < 4; j++)
        row[t + 256 * j] = __floats2half2_rn(v[j].x * inv, v[j].y * inv);
}

// ---------------------------------------------------------------------------
// FP16 tensor-core GEMM, 4-stage cp.async pipeline.
//   C = alpha * A[M,K] @ B[N,K]^T      (A, B fp16, K-contiguous)
// 128x128 CTA tile, BK=32, 8 warps (2m x 4n), 64x32 warp tiles,
// mma.sync.m16n8k16.f32.f16.f16.f32.
// mode: 0 = fp32 store, 1 = fp16 store, 2 = RoPE + fp16 store,
//       3 = fp16 transposed store (V^T, per-batch [D][S])
// M,N % 128 == 0; K % 32 == 0, K >= 96.  grid = (N/128, M/128, batch)
// ---------------------------------------------------------------------------
#define CP16(dst_u32, src_ptr) \
    asm volatile("cp.async.cg.shared.global [%0], [%1], 16;" \
                 :: "r"(dst_u32), "l"(src_ptr))
#define CP_COMMIT() asm volatile("cp.async.commit_group;")
#define CP_WAIT2()  asm volatile("cp.async.wait_group 2;")

__global__ void __launch_bounds__(256)
hgemm(const __half* __restrict__ A, const __half* __restrict__ Bm,
      void* __restrict__ Cv, int M, int N, int K,
      long sA, long sB, long sC, float alpha, int mode,
      const float* __restrict__ CT, const float* __restrict__ ST) {
    A  += (long)blockIdx.z * sA;
    Bm += (long)blockIdx.z * sB;
    const int m0 = blockIdx.y * 128;
    const int n0 = blockIdx.x * 128;

    // [row][k] tiles, stride 40 halves (32 data + 8 pad).
    // Fragment LDS.32 banks: (20*row + k/2) % 32 -> all 32 distinct per warp.
    constexpr int STR    = 40;
    constexpr int STAGE  = 128 * STR;   // halves per operand per stage
    constexpr int STAGES = 4;

    extern __shared__ __half sm[];
    __half* As = sm;
    __half* Bs = sm + STAGES * STAGE;

    uint32_t smem_u32;
    asm("{ .reg .u64 t; cvta.to.shared.u64 t, %1; cvt.u32.u64 %0, t; }"
        : "=r"(smem_u32) : "l"(sm));
    const uint32_t aBase = smem_u32;
    const uint32_t bBase = smem_u32 + (uint32_t)STAGES * STAGE * 2u;

    const int t    = threadIdx.x;
    const int lane = t & 31;
    const int warp = t >> 5;
    const int wm   = warp & 1;     // m offset wm*64
    const int wn   = warp >> 1;    // n offset wn*32
    const int g    = lane >> 2;
    const int tg   = lane & 3;

    float acc[4][4][4];
#pragma unroll
    for (int i = 0; i < 4; i++)
#pragma unroll
        for (int j = 0; j < 4; j++)
#pragma unroll
            for (int r = 0; r < 4; r++) acc[i][j][r] = 0.f;

    // copy descriptors: 2 x 16B (8 halves) per operand per stage per thread
    int cRow[2], cOff[2];
#pragma unroll
    for (int r = 0; r < 2; r++) {
        int id = t + 256 * r;       // 0..511
        cRow[r] = id >> 2;          // 0..127
        cOff[r] = (id & 3) * 8;     // half offset within BK=32
    }

    const int nk = K / 32;

    auto issue = [&](int kb_, int st) {
        const int ko = kb_ * 32;
#pragma unroll
        for (int r = 0; r < 2; r++) {
            const __half* srcA = A + (long)(m0 + cRow[r]) * K + ko + cOff[r];
            uint32_t dA = aBase + (uint32_t)(st * STAGE + cRow[r] * STR + cOff[r]) * 2u;
            CP16(dA, srcA);
            const __half* srcB = Bm + (long)(n0 + cRow[r]) * K + ko + cOff[r];
            uint32_t dB = bBase + (uint32_t)(st * STAGE + cRow[r] * STR + cOff[r]) * 2u;
            CP16(dB, srcB);
        }
        CP_COMMIT();
    };

    issue(0, 0);
    issue(1, 1);
    issue(2, 2);
    CP_WAIT2();
    __syncthreads();

    int buf = 0;
    for (int kb = 0; kb < nk; kb++) {
        const __half* AsB = As + buf * STAGE;
        const __half* BsB = Bs + buf * STAGE;

#pragma unroll
        for (int ks = 0; ks < 2; ks++) {
            uint32_t af[4][4], bf[4][2];
            const int k0 = ks * 16 + 2 * tg;
            const int r0 = wm * 64 + g;
#pragma unroll
            for (int i = 0; i < 4; i++) {
                const __half* p = AsB + (r0 + i * 16) * STR + k0;
                af[i][0] = *(const uint32_t*)p;                 // (row, k..k+1)
                af[i][1] = *(const uint32_t*)(p + 8 * STR);     // (row+8, k..k+1)
                af[i][2] = *(const uint32_t*)(p + 8);           // (row, k+8..k+9)
                af[i][3] = *(const uint32_t*)(p + 8 * STR + 8); // (row+8, k+8..)
            }
#pragma unroll
            for (int j = 0; j < 4; j++) {
                const __half* q = BsB + (wn * 32 + j * 8 + g) * STR + k0;
                bf[j][0] = *(const uint32_t*)q;
                bf[j][1] = *(const uint32_t*)(q + 8);
            }
#pragma unroll
            for (int i = 0; i < 4; i++)
#pragma unroll
                for (int j = 0; j < 4; j++) {
                    asm volatile(
                        "mma.sync.aligned.m16n8k16.row.col.f32.f16.f16.f32 "
                        "{%0,%1,%2,%3}, {%4,%5,%6,%7}, {%8,%9}, {%0,%1,%2,%3};"
                        : "+f"(acc[i][j][0]), "+f"(acc[i][j][1]),
                          "+f"(acc[i][j][2]), "+f"(acc[i][j][3])
                        : "r"(af[i][0]), "r"(af[i][1]), "r"(af[i][2]), "r"(af[i][3]),
                          "r"(bf[j][0]), "r"(bf[j][1]));
                }
        }

        if (kb + 3 < nk) issue(kb + 3, (kb + 3) & 3);
        else             CP_COMMIT();   // empty group keeps wait arithmetic exact
        CP_WAIT2();
        __syncthreads();
        buf = (buf + 1) & 3;
    }

    // ---- epilogue ----
    float* Cf  = (float*)Cv  + (long)blockIdx.z * sC;
    __half* Ch = (__half*)Cv + (long)blockIdx.z * sC;
#pragma unroll
    for (int i = 0; i < 4; i++)
#pragma unroll
        for (int j = 0; j < 4; j++) {
            const int row = m0 + wm * 64 + i * 16 + g;
            const int col = n0 + wn * 32 + j * 8 + 2 * tg;
            float s0 = acc[i][j][0] * alpha, s1 = acc[i][j][1] * alpha;
            float s2 = acc[i][j][2] * alpha, s3 = acc[i][j][3] * alpha;
            if (mode == 0) {
                *(float2*)(Cf + (long)row * N + col)       = make_float2(s0, s1);
                *(float2*)(Cf + (long)(row + 8) * N + col) = make_float2(s2, s3);
            } else if (mode == 3) {
                // V^T store: Vt[b][col][s], s = row within batch
                const int b  = row >> 11;           // SS = 2048
                const int sl = row & (SS - 1);
                __half* base = (__half*)Cv + ((long)b * DD + col) * SS;
                base[sl]          = __float2half_rn(s0);
                base[SS + sl]     = __float2half_rn(s1);   // col+1
                base[sl + 8]      = __float2half_rn(s2);
                base[SS + sl + 8] = __float2half_rn(s3);
            } else {
                if (mode == 2) {
                    const int p   = col >> 1;
                    const int sq0 = row & (SS - 1);
                    const int sq1 = (row + 8) & (SS - 1);
                    float c0v = CT[sq0 * HALFD + p], s0v = ST[sq0 * HALFD + p];
                    float c1v = CT[sq1 * HALFD + p], s1v = ST[sq1 * HALFD + p];
                    float o0 = s0 * c0v - s1 * s0v;
                    float o1 = s0 * s0v + s1 * c0v;
                    float o2 = s2 * c1v - s3 * s1v;
                    float o3 = s2 * s1v + s3 * c1v;
                    s0 = o0; s1 = o1; s2 = o2; s3 = o3;
                }
                *(__half2*)(Ch + (long)row * N + col)       = __floats2half2_rn(s0, s1);
                *(__half2*)(Ch + (long)(row + 8) * N + col) = __floats2half2_rn(s2, s3);
            }
        }
}

// ---------------------------------------------------------------------------
// kernel_launch: x, wq, wk, wv, wo  ->  out [B,S,D] fp32
// ---------------------------------------------------------------------------
extern "C" void kernel_launch(void* const* d_in, const int* in_sizes, int n_in,
                              void* d_out, int out_size) {
    const float* x  = (const float*)d_in[0];
    const float* w_in[4] = {(const float*)d_in[1], (const float*)d_in[2],
                            (const float*)d_in[3], (const float*)d_in[4]};
    float* out = (float*)d_out;

    __half *Q, *K, *Vt, *O, *Xh, *Wh, *P;
    float *CT, *ST;
    cudaGetSymbolAddress((void**)&Q,  g_Q);
    cudaGetSymbolAddress((void**)&K,  g_K);
    cudaGetSymbolAddress((void**)&Vt, g_Vt);
    cudaGetSymbolAddress((void**)&O,  g_O);
    cudaGetSymbolAddress((void**)&Xh, g_Xh);
    cudaGetSymbolAddress((void**)&Wh, g_Wh);
    cudaGetSymbolAddress((void**)&P,  g_P);
    cudaGetSymbolAddress((void**)&CT, g_cos);
    cudaGetSymbolAddress((void**)&ST, g_sin);

    const long SD  = (long)SS * DD;
    const long SSs = (long)SS * SS;

    const int smemB = 4 * 2 * (128 * 40) * 2;   // 81920 bytes
    cudaFuncSetAttribute(hgemm, cudaFuncAttributeMaxDynamicSharedMemorySize, smemB);

    rope_table_kernel<<<SS, HALFD>>>(CT, ST);

    // convert inputs to fp16
    {
        int n4 = BB * SS * DD / 4;
        to_half_kernel<<<(n4 + 255) / 256, 256>>>(x, Xh, n4);
        int w4 = DD * DD / 4;
        for (int i = 0; i < 4; i++)
            to_half_kernel<<<(w4 + 255) / 256, 256>>>(w_in[i], Wh + (long)i * DD * DD, w4);
    }
    const __half* wq = Wh;
    const __half* wk = Wh + (long)DD * DD;
    const __half* wv = Wh + 2L * DD * DD;
    const __half* wo = Wh + 3L * DD * DD;

    // Q/K/V projections (RoPE fused into Q/K; V stored transposed)
    dim3 gProj(DD / 128, (BB * SS) / 128, 1);
    hgemm<<<gProj, 256, smemB>>>(Xh, wq, Q,  BB * SS, DD, DD, 0, 0, 0, 1.0f, 2, CT, ST);
    hgemm<<<gProj, 256, smemB>>>(Xh, wk, K,  BB * SS, DD, DD, 0, 0, 0, 1.0f, 2, CT, ST);
    hgemm<<<gProj, 256, smemB>>>(Xh, wv, Vt, BB * SS, DD, DD, 0, 0, 0, 1.0f, 3, CT, ST);

    // scores = (Q @ K^T) / 32, batched over B
    dim3 gScore(SS / 128, SS / 128, BB);
    hgemm<<<gScore, 256, smemB>>>(Q, K, P, SS, SS, DD, SD, SD, SSs, 0.03125f, 1, CT, ST);

    softmax_h_kernel<<<BB * SS, 256>>>(P);

    // O = P @ V = P @ Vt^T, batched
    dim3 gPV(DD / 128, SS / 128, BB);
    hgemm<<<gPV, 256, smemB>>>(P, Vt, O, SS, DD, SS, SSs, (long)DD * SS, SD, 1.0f, 1, CT, ST);

    // out = O @ wo^T  (fp32 store)
    hgemm<<<gProj, 256, smemB>>>(O, wo, out, BB * SS, DD, DD, 0, 0, 0, 1.0f, 0, CT, ST);
}

// round 17
// speedup vs baseline: 1.6364x; 1.0004x over previous
#include <cuda_runtime.h>
#include <cuda_fp16.h>
#include <math.h>
#include <stdint.h>

// Problem constants: x[4,2048,1024], weights [1024,1024]
#define BB   4
#define SS   2048
#define DD   1024
#define HALFD (DD / 2)

// ---------------------------------------------------------------------------
// Scratch (device globals — no cudaMalloc allowed)
// ---------------------------------------------------------------------------
__device__ __half g_Q [BB * SS * DD];
__device__ __half g_K [BB * SS * DD];
__device__ __half g_Vt[BB * DD * SS];          // V transposed per batch [D][S]
__device__ __half g_O [BB * SS * DD];
__device__ __half g_Xh[BB * SS * DD];          // fp16 x
__device__ __half g_Wh[4 * DD * DD];           // fp16 wq,wk,wv,wo
__device__ __half g_P [(long)BB * SS * SS];    // scores / probs
__device__ float  g_cos[SS * HALFD];
__device__ float  g_sin[SS * HALFD];

// ---------------------------------------------------------------------------
// fp32 -> fp16 conversion, float4 -> 2x half2 per thread
// ---------------------------------------------------------------------------
__global__ void to_half_kernel(const float* __restrict__ in,
                               __half* __restrict__ out, int n4) {
    int i = blockIdx.x * blockDim.x + threadIdx.x;
    if (i < n4) {
        float4 v = ((const float4*)in)[i];
        ((__half2*)out)[2 * i]     = __floats2half2_rn(v.x, v.y);
        ((__half2*)out)[2 * i + 1] = __floats2half2_rn(v.z, v.w);
    }
}

// ---------------------------------------------------------------------------
// RoPE cos/sin tables.  grid = SS, block = HALFD
// ---------------------------------------------------------------------------
__global__ void rope_table_kernel(float* __restrict__ ct, float* __restrict__ st) {
    int s = blockIdx.x;
    int p = threadIdx.x;
    double inv = exp(-((double)(2 * p) / (double)DD) * log(10000.0));
    double ang = (double)s * inv;
    ct[s * HALFD + p] = (float)cos(ang);
    st[s * HALFD + p] = (float)sin(ang);
}

// ---------------------------------------------------------------------------
// Row softmax over length SS on fp16 data. grid = BB*SS rows, block = 256
// ---------------------------------------------------------------------------
__global__ void softmax_h_kernel(__half* __restrict__ P) {
    __half2* row = (__half2*)(P + (long)blockIdx.x * SS);   // 1024 half2
    int t = threadIdx.x;
    float2 v[4];
    float m = -1e30f;
#pragma unroll
    for (int j = 0; j < 4; j++) {
        v[j] = __half22float2(row[t + 256 * j]);
        m = fmaxf(m, fmaxf(v[j].x, v[j].y));
    }
    __shared__ float red[8];
#pragma unroll
    for (int o = 16; o > 0; o >>= 1)
        m = fmaxf(m, __shfl_xor_sync(0xffffffffu, m, o));
    if ((t & 31) == 0) red[t >> 5] = m;
    __syncthreads();
    m = red[0];
#pragma unroll
    for (int i = 1; i < 8; i++) m = fmaxf(m, red[i]);

    float sum = 0.f;
#pragma unroll
    for (int j = 0; j < 4; j++) {
        v[j].x = expf(v[j].x - m);
        v[j].y = expf(v[j].y - m);
        sum += v[j].x + v[j].y;
    }
#pragma unroll
    for (int o = 16; o > 0; o >>= 1)
        sum += __shfl_xor_sync(0xffffffffu, sum, o);
    __syncthreads();                 // all max-reads of red[] done
    if ((t & 31) == 0) red[t >> 5] = sum;
    __syncthreads();
    sum = 0.f;
#pragma unroll
    for (int i = 0; i < 8; i++) sum += red[i];
    float inv = 1.0f / sum;
#pragma unroll
    for (int j = 0; j < 4; j++)
        row[t + 256 * j] = __floats2half2_rn(v[j].x * inv, v[j].y * inv);
}

// ---------------------------------------------------------------------------
// FP16 tensor-core GEMM, 4-stage cp.async pipeline.
//   C = alpha * A[M,K] @ B[N,K]^T      (A, B fp16, K-contiguous)
// 128x128 CTA tile, BK=32, 8 warps (2m x 4n), 64x32 warp tiles,
// mma.sync.m16n8k16.f32.f16.f16.f32.
// mode: 0 = fp32 store, 1 = fp16 store, 2 = RoPE + fp16 store,
//       3 = fp16 transposed store (V^T, per-batch [D][S])
// M,N % 128 == 0; K % 32 == 0, K >= 96.  grid = (N/128, M/128, batch)
// ---------------------------------------------------------------------------
#define CP16(dst_u32, src_ptr) \
    asm volatile("cp.async.cg.shared.global [%0], [%1], 16;" \
                 :: "r"(dst_u32), "l"(src_ptr))
#define CP_COMMIT() asm volatile("cp.async.commit_group;")
#define CP_WAIT2()  asm volatile("cp.async.wait_group 2;")

__global__ void __launch_bounds__(256)
hgemm(const __half* __restrict__ A, const __half* __restrict__ Bm,
      void* __restrict__ Cv, int M, int N, int K,
      long sA, long sB, long sC, float alpha, int mode,
      const float* __restrict__ CT, const float* __restrict__ ST) {
    A  += (long)blockIdx.z * sA;
    Bm += (long)blockIdx.z * sB;
    const int m0 = blockIdx.y * 128;
    const int n0 = blockIdx.x * 128;

    // [row][k] tiles, stride 40 halves (32 data + 8 pad).
    // Fragment LDS.32 banks: (20*row + k/2) % 32 -> all 32 distinct per warp.
    constexpr int STR    = 40;
    constexpr int STAGE  = 128 * STR;   // halves per operand per stage
    constexpr int STAGES = 4;

    extern __shared__ __half sm[];
    __half* As = sm;
    __half* Bs = sm + STAGES * STAGE;

    uint32_t smem_u32;
    asm("{ .reg .u64 t; cvta.to.shared.u64 t, %1; cvt.u32.u64 %0, t; }"
        : "=r"(smem_u32) : "l"(sm));
    const uint32_t aBase = smem_u32;
    const uint32_t bBase = smem_u32 + (uint32_t)STAGES * STAGE * 2u;

    const int t    = threadIdx.x;
    const int lane = t & 31;
    const int warp = t >> 5;
    const int wm   = warp & 1;     // m offset wm*64
    const int wn   = warp >> 1;    // n offset wn*32
    const int g    = lane >> 2;
    const int tg   = lane & 3;

    float acc[4][4][4];
#pragma unroll
    for (int i = 0; i < 4; i++)
#pragma unroll
        for (int j = 0; j < 4; j++)
#pragma unroll
            for (int r = 0; r < 4; r++) acc[i][j][r] = 0.f;

    // copy descriptors: 2 x 16B (8 halves) per operand per stage per thread
    int cRow[2], cOff[2];
#pragma unroll
    for (int r = 0; r < 2; r++) {
        int id = t + 256 * r;       // 0..511
        cRow[r] = id >> 2;          // 0..127
        cOff[r] = (id & 3) * 8;     // half offset within BK=32
    }

    const int nk = K / 32;

    auto issue = [&](int kb_, int st) {
        const int ko = kb_ * 32;
#pragma unroll
        for (int r = 0; r < 2; r++) {
            const __half* srcA = A + (long)(m0 + cRow[r]) * K + ko + cOff[r];
            uint32_t dA = aBase + (uint32_t)(st * STAGE + cRow[r] * STR + cOff[r]) * 2u;
            CP16(dA, srcA);
            const __half* srcB = Bm + (long)(n0 + cRow[r]) * K + ko + cOff[r];
            uint32_t dB = bBase + (uint32_t)(st * STAGE + cRow[r] * STR + cOff[r]) * 2u;
            CP16(dB, srcB);
        }
        CP_COMMIT();
    };

    issue(0, 0);
    issue(1, 1);
    issue(2, 2);
    CP_WAIT2();
    __syncthreads();

    int buf = 0;
    for (int kb = 0; kb < nk; kb++) {
        const __half* AsB = As + buf * STAGE;
        const __half* BsB = Bs + buf * STAGE;

#pragma unroll
        for (int ks = 0; ks < 2; ks++) {
            uint32_t af[4][4], bf[4][2];
            const int k0 = ks * 16 + 2 * tg;
            const int r0 = wm * 64 + g;
#pragma unroll
            for (int i = 0; i < 4; i++) {
                const __half* p = AsB + (r0 + i * 16) * STR + k0;
                af[i][0] = *(const uint32_t*)p;                 // (row, k..k+1)
                af[i][1] = *(const uint32_t*)(p + 8 * STR);     // (row+8, k..k+1)
                af[i][2] = *(const uint32_t*)(p + 8);           // (row, k+8..k+9)
                af[i][3] = *(const uint32_t*)(p + 8 * STR + 8); // (row+8, k+8..)
            }
#pragma unroll
            for (int j = 0; j < 4; j++) {
                const __half* q = BsB + (wn * 32 + j * 8 + g) * STR + k0;
                bf[j][0] = *(const uint32_t*)q;
                bf[j][1] = *(const uint32_t*)(q + 8);
            }
#pragma unroll
            for (int i = 0; i < 4; i++)
#pragma unroll
                for (int j = 0; j < 4; j++) {
                    asm volatile(
                        "mma.sync.aligned.m16n8k16.row.col.f32.f16.f16.f32 "
                        "{%0,%1,%2,%3}, {%4,%5,%6,%7}, {%8,%9}, {%0,%1,%2,%3};"
                        : "+f"(acc[i][j][0]), "+f"(acc[i][j][1]),
                          "+f"(acc[i][j][2]), "+f"(acc[i][j][3])
                        : "r"(af[i][0]), "r"(af[i][1]), "r"(af[i][2]), "r"(af[i][3]),
                          "r"(bf[j][0]), "r"(bf[j][1]));
                }
        }

        if (kb + 3 < nk) issue(kb + 3, (kb + 3) & 3);
        else             CP_COMMIT();   // empty group keeps wait arithmetic exact
        CP_WAIT2();
        __syncthreads();
        buf = (buf + 1) & 3;
    }

    // ---- epilogue ----
    float* Cf  = (float*)Cv  + (long)blockIdx.z * sC;
    __half* Ch = (__half*)Cv + (long)blockIdx.z * sC;
#pragma unroll
    for (int i = 0; i < 4; i++)
#pragma unroll
        for (int j = 0; j < 4; j++) {
            const int row = m0 + wm * 64 + i * 16 + g;
            const int col = n0 + wn * 32 + j * 8 + 2 * tg;
            float s0 = acc[i][j][0] * alpha, s1 = acc[i][j][1] * alpha;
            float s2 = acc[i][j][2] * alpha, s3 = acc[i][j][3] * alpha;
            if (mode == 0) {
                *(float2*)(Cf + (long)row * N + col)       = make_float2(s0, s1);
                *(float2*)(Cf + (long)(row + 8) * N + col) = make_float2(s2, s3);
            } else if (mode == 3) {
                // V^T store: Vt[b][col][s], s = row within batch
                const int b  = row >> 11;           // SS = 2048
                const int sl = row & (SS - 1);
                __half* base = (__half*)Cv + ((long)b * DD + col) * SS;
                base[sl]          = __float2half_rn(s0);
                base[SS + sl]     = __float2half_rn(s1);   // col+1
                base[sl + 8]      = __float2half_rn(s2);
                base[SS + sl + 8] = __float2half_rn(s3);
            } else {
                if (mode == 2) {
                    const int p   = col >> 1;
                    const int sq0 = row & (SS - 1);
                    const int sq1 = (row + 8) & (SS - 1);
                    float c0v = CT[sq0 * HALFD + p], s0v = ST[sq0 * HALFD + p];
                    float c1v = CT[sq1 * HALFD + p], s1v = ST[sq1 * HALFD + p];
                    float o0 = s0 * c0v - s1 * s0v;
                    float o1 = s0 * s0v + s1 * c0v;
                    float o2 = s2 * c1v - s3 * s1v;
                    float o3 = s2 * s1v + s3 * c1v;
                    s0 = o0; s1 = o1; s2 = o2; s3 = o3;
                }
                *(__half2*)(Ch + (long)row * N + col)       = __floats2half2_rn(s0, s1);
                *(__half2*)(Ch + (long)(row + 8) * N + col) = __floats2half2_rn(s2, s3);
            }
        }
}

// ---------------------------------------------------------------------------
// kernel_launch: x, wq, wk, wv, wo  ->  out [B,S,D] fp32
// ---------------------------------------------------------------------------
extern "C" void kernel_launch(void* const* d_in, const int* in_sizes, int n_in,
                              void* d_out, int out_size) {
    const float* x  = (const float*)d_in[0];
    const float* w_in[4] = {(const float*)d_in[1], (const float*)d_in[2],
                            (const float*)d_in[3], (const float*)d_in[4]};
    float* out = (float*)d_out;

    __half *Q, *K, *Vt, *O, *Xh, *Wh, *P;
    float *CT, *ST;
    cudaGetSymbolAddress((void**)&Q,  g_Q);
    cudaGetSymbolAddress((void**)&K,  g_K);
    cudaGetSymbolAddress((void**)&Vt, g_Vt);
    cudaGetSymbolAddress((void**)&O,  g_O);
    cudaGetSymbolAddress((void**)&Xh, g_Xh);
    cudaGetSymbolAddress((void**)&Wh, g_Wh);
    cudaGetSymbolAddress((void**)&P,  g_P);
    cudaGetSymbolAddress((void**)&CT, g_cos);
    cudaGetSymbolAddress((void**)&ST, g_sin);

    const long SD  = (long)SS * DD;
    const long SSs = (long)SS * SS;

    const int smemB = 4 * 2 * (128 * 40) * 2;   // 81920 bytes
    cudaFuncSetAttribute(hgemm, cudaFuncAttributeMaxDynamicSharedMemorySize, smemB);

    rope_table_kernel<<<SS, HALFD>>>(CT, ST);

    // convert inputs to fp16
    {
        int n4 = BB * SS * DD / 4;
        to_half_kernel<<<(n4 + 255) / 256, 256>>>(x, Xh, n4);
        int w4 = DD * DD / 4;
        for (int i = 0; i < 4; i++)
            to_half_kernel<<<(w4 + 255) / 256, 256>>>(w_in[i], Wh + (long)i * DD * DD, w4);
    }
    const __half* wq = Wh;
    const __half* wk = Wh + (long)DD * DD;
    const __half* wv = Wh + 2L * DD * DD;
    const __half* wo = Wh + 3L * DD * DD;

    // Q/K/V projections (RoPE fused into Q/K; V stored transposed)
    dim3 gProj(DD / 128, (BB * SS) / 128, 1);
    hgemm<<<gProj, 256, smemB>>>(Xh, wq, Q,  BB * SS, DD, DD, 0, 0, 0, 1.0f, 2, CT, ST);
    hgemm<<<gProj, 256, smemB>>>(Xh, wk, K,  BB * SS, DD, DD, 0, 0, 0, 1.0f, 2, CT, ST);
    hgemm<<<gProj, 256, smemB>>>(Xh, wv, Vt, BB * SS, DD, DD, 0, 0, 0, 1.0f, 3, CT, ST);

    // scores = (Q @ K^T) / 32, batched over B
    dim3 gScore(SS / 128, SS / 128, BB);
    hgemm<<<gScore, 256, smemB>>>(Q, K, P, SS, SS, DD, SD, SD, SSs, 0.03125f, 1, CT, ST);

    softmax_h_kernel<<<BB * SS, 256>>>(P);

    // O = P @ V = P @ Vt^T, batched
    dim3 gPV(DD / 128, SS / 128, BB);
    hgemm<<<gPV, 256, smemB>>>(P, Vt, O, SS, DD, SS, SSs, (long)DD * SS, SD, 1.0f, 1, CT, ST);

    // out = O @ wo^T  (fp32 store)
    hgemm<<<gProj, 256, smemB>>>(O, wo, out, BB * SS, DD, DD, 0, 0, 0, 1.0f, 0, CT, ST);
}